// round 1
// baseline (speedup 1.0000x reference)
#include <cuda_runtime.h>
#include <math.h>

#define B_  2
#define S_  2048
#define DM_ 1024
#define H_  16
#define D_  64

// Scratch (allowed: __device__ globals). Layout [B, H, S, D].
__device__ float g_q[B_*H_*S_*D_];
__device__ float g_k[B_*H_*S_*D_];
__device__ float g_v[B_*H_*S_*D_];

// ---------------------------------------------------------------------------
// Kernel 1: P[m,n] = sum_k X[m,k] * W[n,k]   (X: [4096,1024], W: [1024,1024])
// 128x128x8 tile, 256 threads, 8x8 microtile. Output written in [B,H,S,D].
// ---------------------------------------------------------------------------
__global__ __launch_bounds__(256)
void qkv_gemm(const float* __restrict__ X,
              const float* __restrict__ Wq,
              const float* __restrict__ Wk,
              const float* __restrict__ Wv)
{
    __shared__ float As[8][128];   // [k][m]
    __shared__ float Bs[8][128];   // [k][n]

    const float* W;
    float* out;
    if (blockIdx.z == 0)      { W = Wq; out = g_q; }
    else if (blockIdx.z == 1) { W = Wk; out = g_k; }
    else                      { W = Wv; out = g_v; }

    const int tid = threadIdx.x;
    const int m0  = blockIdx.y * 128;
    const int n0  = blockIdx.x * 128;
    const int lr  = tid >> 1;          // 0..127
    const int lc  = (tid & 1) * 4;     // 0 or 4
    const float* Ap = X + (size_t)(m0 + lr) * DM_ + lc;
    const float* Bp = W + (size_t)(n0 + lr) * DM_ + lc;
    const int tx = tid & 15;
    const int ty = tid >> 4;

    float acc[8][8];
    #pragma unroll
    for (int i = 0; i < 8; i++)
        #pragma unroll
        for (int j = 0; j < 8; j++) acc[i][j] = 0.f;

    for (int k0 = 0; k0 < DM_; k0 += 8) {
        float4 av = *(const float4*)(Ap + k0);
        float4 bv = *(const float4*)(Bp + k0);
        __syncthreads();   // previous compute done before overwrite
        As[lc+0][lr] = av.x; As[lc+1][lr] = av.y;
        As[lc+2][lr] = av.z; As[lc+3][lr] = av.w;
        Bs[lc+0][lr] = bv.x; Bs[lc+1][lr] = bv.y;
        Bs[lc+2][lr] = bv.z; Bs[lc+3][lr] = bv.w;
        __syncthreads();
        #pragma unroll
        for (int kk = 0; kk < 8; kk++) {
            float4 a0 = *(const float4*)&As[kk][ty*4];
            float4 a1 = *(const float4*)&As[kk][64 + ty*4];
            float4 b0 = *(const float4*)&Bs[kk][tx*4];
            float4 b1 = *(const float4*)&Bs[kk][64 + tx*4];
            float ar[8] = {a0.x,a0.y,a0.z,a0.w,a1.x,a1.y,a1.z,a1.w};
            float br[8] = {b0.x,b0.y,b0.z,b0.w,b1.x,b1.y,b1.z,b1.w};
            #pragma unroll
            for (int i = 0; i < 8; i++)
                #pragma unroll
                for (int j = 0; j < 8; j++)
                    acc[i][j] += ar[i] * br[j];
        }
    }

    // Epilogue: scatter to [B,H,S,D]
    #pragma unroll
    for (int i = 0; i < 8; i++) {
        int ml = (i < 4) ? (ty*4 + i) : (64 + ty*4 + i - 4);
        int m  = m0 + ml;
        int b  = m >> 11;            // /2048
        int s  = m & (S_ - 1);
        #pragma unroll
        for (int jh = 0; jh < 2; jh++) {
            int nl = jh * 64 + tx*4;
            int n  = n0 + nl;
            int h  = n >> 6;
            int d  = n & 63;
            float4 v = make_float4(acc[i][jh*4+0], acc[i][jh*4+1],
                                   acc[i][jh*4+2], acc[i][jh*4+3]);
            *(float4*)&out[(((size_t)(b*H_ + h))*S_ + s)*D_ + d] = v;
        }
    }
}

// ---------------------------------------------------------------------------
// Kernel 2: RoPE (in-place on g_q/g_k), Q scaled by D^-0.5 = 1/8.
// One thread per (b,h,s,d2) pair, d2 in [0,32).
// ---------------------------------------------------------------------------
__global__ __launch_bounds__(256)
void rope_kernel(const int* __restrict__ pos_ids)
{
    int idx = blockIdx.x * blockDim.x + threadIdx.x;
    const int total = B_ * H_ * S_ * 32;
    if (idx >= total) return;

    int d2 = idx & 31;
    int s  = (idx >> 5)  & (S_ - 1);
    int b  = idx >> 20;                 // 5 + 11 + 4 bits below

    int pos = pos_ids[b * S_ + s];
    // inv_freq = 10000^(-d2/32), computed in double to track jax's fp32 value
    float inv = (float)exp(-(double)d2 * (log(10000.0) / 32.0));
    float ang = (float)pos * inv;
    float sn, cs;
    sincosf(ang, &sn, &cs);

    int base = (idx >> 5) << 6;         // ((b*H+h)*S + s) * 64

    float q1 = g_q[base + d2];
    float q2 = g_q[base + 32 + d2];
    g_q[base + d2]      = 0.125f * (q1 * cs - q2 * sn);
    g_q[base + 32 + d2] = 0.125f * (q2 * cs + q1 * sn);

    float k1 = g_k[base + d2];
    float k2 = g_k[base + 32 + d2];
    g_k[base + d2]      = k1 * cs - k2 * sn;
    g_k[base + 32 + d2] = k2 * cs + k1 * sn;
}

// ---------------------------------------------------------------------------
// Kernel 3: flash attention, 64q x 64k tiles, fp32, online softmax.
// SMEM (dynamic, exactly 48KB): Qs[d][q] 64x64, KP[.]64x64 (K^T, then P^T),
// Vs[k][d] 64x64.
// ---------------------------------------------------------------------------
__global__ __launch_bounds__(256)
void attn_kernel(const float* __restrict__ mask, float* __restrict__ outp)
{
    extern __shared__ float sm[];
    float* Qs = sm;                // [64][64]  (d-major: Qs[d*64 + q])
    float* KP = sm + 64*64;        // [64][64]  Ks[d*64+k], later Ps[k*64+q]
    float* Vs = sm + 2*64*64;      // [64][64]  Vs[k*64+d]

    const int tid = threadIdx.x;
    const int tx  = tid & 15;
    const int ty  = tid >> 4;
    const int b   = blockIdx.z;
    const int h   = blockIdx.y;
    const int q0  = blockIdx.x * 64;

    const float* Qg = g_q + (((size_t)(b*H_ + h))*S_ + q0) * D_;
    const float* Kg = g_k + (((size_t)(b*H_ + h))*S_) * D_;
    const float* Vg = g_v + (((size_t)(b*H_ + h))*S_) * D_;
    const float* Mg = mask + ((size_t)b * S_ + q0) * S_;

    // Load Q tile (transposed to [d][q])
    {
        int r = tid >> 2;                  // 0..63 query row
        #pragma unroll
        for (int it = 0; it < 4; it++) {
            int c4 = (tid & 3) + it * 4;   // float4 index 0..15
            float4 v = *(const float4*)(Qg + r * D_ + c4 * 4);
            int d = c4 * 4;
            Qs[(d+0)*64 + r] = v.x; Qs[(d+1)*64 + r] = v.y;
            Qs[(d+2)*64 + r] = v.z; Qs[(d+3)*64 + r] = v.w;
        }
    }

    float m_i[4], l_i[4], o[4][4];
    #pragma unroll
    for (int i = 0; i < 4; i++) {
        m_i[i] = -1e30f; l_i[i] = 0.f;
        #pragma unroll
        for (int j = 0; j < 4; j++) o[i][j] = 0.f;
    }

    for (int t = 0; t < S_ / 64; t++) {
        const int kbase = t * 64;
        __syncthreads();  // also covers Q-tile stores on t=0, Vs/Ps reuse later

        // Load K tile transposed, V tile straight
        {
            int r = tid >> 2;
            #pragma unroll
            for (int it = 0; it < 4; it++) {
                int c4 = (tid & 3) + it * 4;
                float4 kv = *(const float4*)(Kg + (size_t)(kbase + r) * D_ + c4*4);
                int d = c4 * 4;
                KP[(d+0)*64 + r] = kv.x; KP[(d+1)*64 + r] = kv.y;
                KP[(d+2)*64 + r] = kv.z; KP[(d+3)*64 + r] = kv.w;
                float4 vv = *(const float4*)(Vg + (size_t)(kbase + r) * D_ + c4*4);
                *(float4*)&Vs[r*64 + c4*4] = vv;
            }
        }
        __syncthreads();

        // Scores: acc[i][j] = sum_d Q[q][d] K[k][d]
        float acc[4][4];
        #pragma unroll
        for (int i = 0; i < 4; i++)
            #pragma unroll
            for (int j = 0; j < 4; j++) acc[i][j] = 0.f;

        #pragma unroll 8
        for (int dd = 0; dd < 64; dd++) {
            float4 qv = *(const float4*)&Qs[dd*64 + ty*4];
            float4 kv = *(const float4*)&KP[dd*64 + tx*4];
            float qa[4] = {qv.x, qv.y, qv.z, qv.w};
            float ka[4] = {kv.x, kv.y, kv.z, kv.w};
            #pragma unroll
            for (int i = 0; i < 4; i++)
                #pragma unroll
                for (int j = 0; j < 4; j++)
                    acc[i][j] += qa[i] * ka[j];
        }

        // Add mask + online softmax (rows owned by same-ty 16-lane groups)
        #pragma unroll
        for (int i = 0; i < 4; i++) {
            float4 mv = *(const float4*)(Mg + (size_t)(ty*4 + i) * S_ + kbase + tx*4);
            acc[i][0] += mv.x; acc[i][1] += mv.y;
            acc[i][2] += mv.z; acc[i][3] += mv.w;

            float rmax = fmaxf(fmaxf(acc[i][0], acc[i][1]),
                               fmaxf(acc[i][2], acc[i][3]));
            #pragma unroll
            for (int off = 8; off >= 1; off >>= 1)
                rmax = fmaxf(rmax, __shfl_xor_sync(0xffffffffu, rmax, off, 16));

            float mnew = fmaxf(m_i[i], rmax);
            float rsum = 0.f;
            #pragma unroll
            for (int j = 0; j < 4; j++) {
                acc[i][j] = __expf(acc[i][j] - mnew);
                rsum += acc[i][j];
            }
            #pragma unroll
            for (int off = 8; off >= 1; off >>= 1)
                rsum += __shfl_xor_sync(0xffffffffu, rsum, off, 16);

            float alpha = __expf(m_i[i] - mnew);
            l_i[i] = l_i[i] * alpha + rsum;
            m_i[i] = mnew;
            #pragma unroll
            for (int j = 0; j < 4; j++) o[i][j] *= alpha;
        }

        __syncthreads();   // everyone done reading Ks before P overwrites it

        // Write P transposed: Ps[k][q]
        #pragma unroll
        for (int i = 0; i < 4; i++)
            #pragma unroll
            for (int j = 0; j < 4; j++)
                KP[(tx*4 + j)*64 + (ty*4 + i)] = acc[i][j];
        __syncthreads();

        // o[q][d] += sum_k P[q][k] * V[k][d]
        #pragma unroll 8
        for (int kk = 0; kk < 64; kk++) {
            float4 pv = *(const float4*)&KP[kk*64 + ty*4];
            float4 vv = *(const float4*)&Vs[kk*64 + tx*4];
            float pa[4] = {pv.x, pv.y, pv.z, pv.w};
            float va[4] = {vv.x, vv.y, vv.z, vv.w};
            #pragma unroll
            for (int i = 0; i < 4; i++)
                #pragma unroll
                for (int j = 0; j < 4; j++)
                    o[i][j] += pa[i] * va[j];
        }
    }

    // Normalize and write ctx: out[b][s][h*64 + d]
    #pragma unroll
    for (int i = 0; i < 4; i++) {
        float inv_l = 1.f / l_i[i];
        int q = q0 + ty*4 + i;
        float4 res = make_float4(o[i][0]*inv_l, o[i][1]*inv_l,
                                 o[i][2]*inv_l, o[i][3]*inv_l);
        *(float4*)&outp[((size_t)b * S_ + q) * DM_ + h*64 + tx*4] = res;
    }
}

// ---------------------------------------------------------------------------
extern "C" void kernel_launch(void* const* d_in, const int* in_sizes, int n_in,
                              void* d_out, int out_size)
{
    const float* hidden = (const float*)d_in[0];
    const float* mask   = (const float*)d_in[1];
    const int*   pos    = (const int*)  d_in[2];
    const float* Wq     = (const float*)d_in[3];
    const float* Wk     = (const float*)d_in[4];
    const float* Wv     = (const float*)d_in[5];
    float* out = (float*)d_out;

    dim3 g1(DM_ / 128, (B_ * S_) / 128, 3);
    qkv_gemm<<<g1, 256>>>(hidden, Wq, Wk, Wv);

    int total_pairs = B_ * H_ * S_ * 32;
    rope_kernel<<<(total_pairs + 255) / 256, 256>>>(pos);

    dim3 g2(S_ / 64, H_, B_);
    attn_kernel<<<g2, 256, 3 * 64 * 64 * sizeof(float)>>>(mask, out);
}

// round 2
// speedup vs baseline: 1.6406x; 1.6406x over previous
#include <cuda_runtime.h>
#include <math.h>

#define B_  2
#define S_  2048
#define DM_ 1024
#define H_  16
#define D_  64

// Scratch (allowed: __device__ globals). Layout [B, H, S, D].
__device__ float g_q[B_*H_*S_*D_];
__device__ float g_k[B_*H_*S_*D_];
__device__ float g_v[B_*H_*S_*D_];

// ---------------------------------------------------------------------------
// Kernel 1: P[m,n] = sum_k X[m,k] * W[n,k]   (X: [4096,1024], W: [1024,1024])
// 128x128x8 tile, 256 threads, 8x8 microtile. Output written in [B,H,S,D].
// ---------------------------------------------------------------------------
__global__ __launch_bounds__(256)
void qkv_gemm(const float* __restrict__ X,
              const float* __restrict__ Wq,
              const float* __restrict__ Wk,
              const float* __restrict__ Wv)
{
    __shared__ float As[8][128];   // [k][m]
    __shared__ float Bs[8][128];   // [k][n]

    const float* W;
    float* out;
    if (blockIdx.z == 0)      { W = Wq; out = g_q; }
    else if (blockIdx.z == 1) { W = Wk; out = g_k; }
    else                      { W = Wv; out = g_v; }

    const int tid = threadIdx.x;
    const int m0  = blockIdx.y * 128;
    const int n0  = blockIdx.x * 128;
    const int lr  = tid >> 1;          // 0..127
    const int lc  = (tid & 1) * 4;     // 0 or 4
    const float* Ap = X + (size_t)(m0 + lr) * DM_ + lc;
    const float* Bp = W + (size_t)(n0 + lr) * DM_ + lc;
    const int tx = tid & 15;
    const int ty = tid >> 4;

    float acc[8][8];
    #pragma unroll
    for (int i = 0; i < 8; i++)
        #pragma unroll
        for (int j = 0; j < 8; j++) acc[i][j] = 0.f;

    for (int k0 = 0; k0 < DM_; k0 += 8) {
        float4 av = *(const float4*)(Ap + k0);
        float4 bv = *(const float4*)(Bp + k0);
        __syncthreads();   // previous compute done before overwrite
        As[lc+0][lr] = av.x; As[lc+1][lr] = av.y;
        As[lc+2][lr] = av.z; As[lc+3][lr] = av.w;
        Bs[lc+0][lr] = bv.x; Bs[lc+1][lr] = bv.y;
        Bs[lc+2][lr] = bv.z; Bs[lc+3][lr] = bv.w;
        __syncthreads();
        #pragma unroll
        for (int kk = 0; kk < 8; kk++) {
            float4 a0 = *(const float4*)&As[kk][ty*4];
            float4 a1 = *(const float4*)&As[kk][64 + ty*4];
            float4 b0 = *(const float4*)&Bs[kk][tx*4];
            float4 b1 = *(const float4*)&Bs[kk][64 + tx*4];
            float ar[8] = {a0.x,a0.y,a0.z,a0.w,a1.x,a1.y,a1.z,a1.w};
            float br[8] = {b0.x,b0.y,b0.z,b0.w,b1.x,b1.y,b1.z,b1.w};
            #pragma unroll
            for (int i = 0; i < 8; i++)
                #pragma unroll
                for (int j = 0; j < 8; j++)
                    acc[i][j] += ar[i] * br[j];
        }
    }

    // Epilogue: scatter to [B,H,S,D]
    #pragma unroll
    for (int i = 0; i < 8; i++) {
        int ml = (i < 4) ? (ty*4 + i) : (64 + ty*4 + i - 4);
        int m  = m0 + ml;
        int b  = m >> 11;            // /2048
        int s  = m & (S_ - 1);
        #pragma unroll
        for (int jh = 0; jh < 2; jh++) {
            int nl = jh * 64 + tx*4;
            int n  = n0 + nl;
            int h  = n >> 6;
            int d  = n & 63;
            float4 v = make_float4(acc[i][jh*4+0], acc[i][jh*4+1],
                                   acc[i][jh*4+2], acc[i][jh*4+3]);
            *(float4*)&out[(((size_t)(b*H_ + h))*S_ + s)*D_ + d] = v;
        }
    }
}

// ---------------------------------------------------------------------------
// Kernel 2: RoPE (in-place on g_q/g_k), Q scaled by D^-0.5 = 1/8.
// One thread per (b,h,s,d2) pair, d2 in [0,32).
// ---------------------------------------------------------------------------
__global__ __launch_bounds__(256)
void rope_kernel(const int* __restrict__ pos_ids)
{
    int idx = blockIdx.x * blockDim.x + threadIdx.x;
    const int total = B_ * H_ * S_ * 32;
    if (idx >= total) return;

    int d2 = idx & 31;
    int s  = (idx >> 5)  & (S_ - 1);
    int b  = idx >> 20;                 // 5 + 11 + 4 bits below

    int pos = pos_ids[b * S_ + s];
    // inv_freq = 10000^(-d2/32), computed in double to track jax's fp32 value
    float inv = (float)exp(-(double)d2 * (log(10000.0) / 32.0));
    float ang = (float)pos * inv;
    float sn, cs;
    sincosf(ang, &sn, &cs);

    int base = (idx >> 5) << 6;         // ((b*H+h)*S + s) * 64

    float q1 = g_q[base + d2];
    float q2 = g_q[base + 32 + d2];
    g_q[base + d2]      = 0.125f * (q1 * cs - q2 * sn);
    g_q[base + 32 + d2] = 0.125f * (q2 * cs + q1 * sn);

    float k1 = g_k[base + d2];
    float k2 = g_k[base + 32 + d2];
    g_k[base + d2]      = k1 * cs - k2 * sn;
    g_k[base + 32 + d2] = k2 * cs + k1 * sn;
}

// ---------------------------------------------------------------------------
// Kernel 3: flash attention, 64q x 64k tiles, fp32, online softmax.
// SMEM (dynamic, exactly 48KB): Qs[d][q] 64x64, KP[.]64x64 (K^T, then P^T),
// Vs[k][d] 64x64.
// ---------------------------------------------------------------------------
__global__ __launch_bounds__(256)
void attn_kernel(const float* __restrict__ mask, float* __restrict__ outp)
{
    extern __shared__ float sm[];
    float* Qs = sm;                // [64][64]  (d-major: Qs[d*64 + q])
    float* KP = sm + 64*64;        // [64][64]  Ks[d*64+k], later Ps[k*64+q]
    float* Vs = sm + 2*64*64;      // [64][64]  Vs[k*64+d]

    const int tid = threadIdx.x;
    const int tx  = tid & 15;
    const int ty  = tid >> 4;
    const int b   = blockIdx.z;
    const int h   = blockIdx.y;
    const int q0  = blockIdx.x * 64;

    const float* Qg = g_q + (((size_t)(b*H_ + h))*S_ + q0) * D_;
    const float* Kg = g_k + (((size_t)(b*H_ + h))*S_) * D_;
    const float* Vg = g_v + (((size_t)(b*H_ + h))*S_) * D_;
    const float* Mg = mask + ((size_t)b * S_ + q0) * S_;

    // Load Q tile (transposed to [d][q])
    {
        int r = tid >> 2;                  // 0..63 query row
        #pragma unroll
        for (int it = 0; it < 4; it++) {
            int c4 = (tid & 3) + it * 4;   // float4 index 0..15
            float4 v = *(const float4*)(Qg + r * D_ + c4 * 4);
            int d = c4 * 4;
            Qs[(d+0)*64 + r] = v.x; Qs[(d+1)*64 + r] = v.y;
            Qs[(d+2)*64 + r] = v.z; Qs[(d+3)*64 + r] = v.w;
        }
    }

    float m_i[4], l_i[4], o[4][4];
    #pragma unroll
    for (int i = 0; i < 4; i++) {
        m_i[i] = -1e30f; l_i[i] = 0.f;
        #pragma unroll
        for (int j = 0; j < 4; j++) o[i][j] = 0.f;
    }

    for (int t = 0; t < S_ / 64; t++) {
        const int kbase = t * 64;
        __syncthreads();  // also covers Q-tile stores on t=0, Vs/Ps reuse later

        // Load K tile transposed, V tile straight
        {
            int r = tid >> 2;
            #pragma unroll
            for (int it = 0; it < 4; it++) {
                int c4 = (tid & 3) + it * 4;
                float4 kv = *(const float4*)(Kg + (size_t)(kbase + r) * D_ + c4*4);
                int d = c4 * 4;
                KP[(d+0)*64 + r] = kv.x; KP[(d+1)*64 + r] = kv.y;
                KP[(d+2)*64 + r] = kv.z; KP[(d+3)*64 + r] = kv.w;
                float4 vv = *(const float4*)(Vg + (size_t)(kbase + r) * D_ + c4*4);
                *(float4*)&Vs[r*64 + c4*4] = vv;
            }
        }
        __syncthreads();

        // Scores: acc[i][j] = sum_d Q[q][d] K[k][d]
        float acc[4][4];
        #pragma unroll
        for (int i = 0; i < 4; i++)
            #pragma unroll
            for (int j = 0; j < 4; j++) acc[i][j] = 0.f;

        #pragma unroll 8
        for (int dd = 0; dd < 64; dd++) {
            float4 qv = *(const float4*)&Qs[dd*64 + ty*4];
            float4 kv = *(const float4*)&KP[dd*64 + tx*4];
            float qa[4] = {qv.x, qv.y, qv.z, qv.w};
            float ka[4] = {kv.x, kv.y, kv.z, kv.w};
            #pragma unroll
            for (int i = 0; i < 4; i++)
                #pragma unroll
                for (int j = 0; j < 4; j++)
                    acc[i][j] += qa[i] * ka[j];
        }

        // Add mask + online softmax (rows owned by same-ty 16-lane groups)
        #pragma unroll
        for (int i = 0; i < 4; i++) {
            float4 mv = *(const float4*)(Mg + (size_t)(ty*4 + i) * S_ + kbase + tx*4);
            acc[i][0] += mv.x; acc[i][1] += mv.y;
            acc[i][2] += mv.z; acc[i][3] += mv.w;

            float rmax = fmaxf(fmaxf(acc[i][0], acc[i][1]),
                               fmaxf(acc[i][2], acc[i][3]));
            #pragma unroll
            for (int off = 8; off >= 1; off >>= 1)
                rmax = fmaxf(rmax, __shfl_xor_sync(0xffffffffu, rmax, off, 16));

            float mnew = fmaxf(m_i[i], rmax);
            float rsum = 0.f;
            #pragma unroll
            for (int j = 0; j < 4; j++) {
                acc[i][j] = __expf(acc[i][j] - mnew);
                rsum += acc[i][j];
            }
            #pragma unroll
            for (int off = 8; off >= 1; off >>= 1)
                rsum += __shfl_xor_sync(0xffffffffu, rsum, off, 16);

            float alpha = __expf(m_i[i] - mnew);
            l_i[i] = l_i[i] * alpha + rsum;
            m_i[i] = mnew;
            #pragma unroll
            for (int j = 0; j < 4; j++) o[i][j] *= alpha;
        }

        __syncthreads();   // everyone done reading Ks before P overwrites it

        // Write P transposed: Ps[k][q]
        #pragma unroll
        for (int i = 0; i < 4; i++)
            #pragma unroll
            for (int j = 0; j < 4; j++)
                KP[(tx*4 + j)*64 + (ty*4 + i)] = acc[i][j];
        __syncthreads();

        // o[q][d] += sum_k P[q][k] * V[k][d]
        #pragma unroll 8
        for (int kk = 0; kk < 64; kk++) {
            float4 pv = *(const float4*)&KP[kk*64 + ty*4];
            float4 vv = *(const float4*)&Vs[kk*64 + tx*4];
            float pa[4] = {pv.x, pv.y, pv.z, pv.w};
            float va[4] = {vv.x, vv.y, vv.z, vv.w};
            #pragma unroll
            for (int i = 0; i < 4; i++)
                #pragma unroll
                for (int j = 0; j < 4; j++)
                    o[i][j] += pa[i] * va[j];
        }
    }

    // Normalize and write ctx: out[b][s][h*64 + d]
    #pragma unroll
    for (int i = 0; i < 4; i++) {
        float inv_l = 1.f / l_i[i];
        int q = q0 + ty*4 + i;
        float4 res = make_float4(o[i][0]*inv_l, o[i][1]*inv_l,
                                 o[i][2]*inv_l, o[i][3]*inv_l);
        *(float4*)&outp[((size_t)b * S_ + q) * DM_ + h*64 + tx*4] = res;
    }
}

// ---------------------------------------------------------------------------
extern "C" void kernel_launch(void* const* d_in, const int* in_sizes, int n_in,
                              void* d_out, int out_size)
{
    const float* hidden = (const float*)d_in[0];
    const float* mask   = (const float*)d_in[1];
    const int*   pos    = (const int*)  d_in[2];
    const float* Wq     = (const float*)d_in[3];
    const float* Wk     = (const float*)d_in[4];
    const float* Wv     = (const float*)d_in[5];
    float* out = (float*)d_out;

    dim3 g1(DM_ / 128, (B_ * S_) / 128, 3);
    qkv_gemm<<<g1, 256>>>(hidden, Wq, Wk, Wv);

    int total_pairs = B_ * H_ * S_ * 32;
    rope_kernel<<<(total_pairs + 255) / 256, 256>>>(pos);

    dim3 g2(S_ / 64, H_, B_);
    attn_kernel<<<g2, 256, 3 * 64 * 64 * sizeof(float)>>>(mask, out);
}

// round 3
// speedup vs baseline: 1.6433x; 1.0017x over previous
#include <cuda_runtime.h>
#include <math.h>

#define B_  2
#define S_  2048
#define DM_ 1024
#define H_  16
#define D_  64

// Scratch (allowed: __device__ globals). Layout [B, H, S, D].
__device__ float g_q[B_*H_*S_*D_];
__device__ float g_k[B_*H_*S_*D_];
__device__ float g_v[B_*H_*S_*D_];

// ---------------------------------------------------------------------------
// Kernel 1: P[m,n] = sum_k X[m,k] * W[n,k]   (X: [4096,1024], W: [1024,1024])
// 128x128x8 tile, 256 threads, 8x8 microtile. Output written in [B,H,S,D].
// ---------------------------------------------------------------------------
__global__ __launch_bounds__(256)
void qkv_gemm(const float* __restrict__ X,
              const float* __restrict__ Wq,
              const float* __restrict__ Wk,
              const float* __restrict__ Wv)
{
    __shared__ float As[8][128];   // [k][m]
    __shared__ float Bs[8][128];   // [k][n]

    const float* W;
    float* out;
    if (blockIdx.z == 0)      { W = Wq; out = g_q; }
    else if (blockIdx.z == 1) { W = Wk; out = g_k; }
    else                      { W = Wv; out = g_v; }

    const int tid = threadIdx.x;
    const int m0  = blockIdx.y * 128;
    const int n0  = blockIdx.x * 128;
    const int lr  = tid >> 1;          // 0..127
    const int lc  = (tid & 1) * 4;     // 0 or 4
    const float* Ap = X + (size_t)(m0 + lr) * DM_ + lc;
    const float* Bp = W + (size_t)(n0 + lr) * DM_ + lc;
    const int tx = tid & 15;
    const int ty = tid >> 4;

    float acc[8][8];
    #pragma unroll
    for (int i = 0; i < 8; i++)
        #pragma unroll
        for (int j = 0; j < 8; j++) acc[i][j] = 0.f;

    for (int k0 = 0; k0 < DM_; k0 += 8) {
        float4 av = *(const float4*)(Ap + k0);
        float4 bv = *(const float4*)(Bp + k0);
        __syncthreads();   // previous compute done before overwrite
        As[lc+0][lr] = av.x; As[lc+1][lr] = av.y;
        As[lc+2][lr] = av.z; As[lc+3][lr] = av.w;
        Bs[lc+0][lr] = bv.x; Bs[lc+1][lr] = bv.y;
        Bs[lc+2][lr] = bv.z; Bs[lc+3][lr] = bv.w;
        __syncthreads();
        #pragma unroll
        for (int kk = 0; kk < 8; kk++) {
            float4 a0 = *(const float4*)&As[kk][ty*4];
            float4 a1 = *(const float4*)&As[kk][64 + ty*4];
            float4 b0 = *(const float4*)&Bs[kk][tx*4];
            float4 b1 = *(const float4*)&Bs[kk][64 + tx*4];
            float ar[8] = {a0.x,a0.y,a0.z,a0.w,a1.x,a1.y,a1.z,a1.w};
            float br[8] = {b0.x,b0.y,b0.z,b0.w,b1.x,b1.y,b1.z,b1.w};
            #pragma unroll
            for (int i = 0; i < 8; i++)
                #pragma unroll
                for (int j = 0; j < 8; j++)
                    acc[i][j] += ar[i] * br[j];
        }
    }

    // Epilogue: scatter to [B,H,S,D]
    #pragma unroll
    for (int i = 0; i < 8; i++) {
        int ml = (i < 4) ? (ty*4 + i) : (64 + ty*4 + i - 4);
        int m  = m0 + ml;
        int b  = m >> 11;            // /2048
        int s  = m & (S_ - 1);
        #pragma unroll
        for (int jh = 0; jh < 2; jh++) {
            int nl = jh * 64 + tx*4;
            int n  = n0 + nl;
            int h  = n >> 6;
            int d  = n & 63;
            float4 v = make_float4(acc[i][jh*4+0], acc[i][jh*4+1],
                                   acc[i][jh*4+2], acc[i][jh*4+3]);
            *(float4*)&out[(((size_t)(b*H_ + h))*S_ + s)*D_ + d] = v;
        }
    }
}

// ---------------------------------------------------------------------------
// Kernel 2: RoPE (in-place on g_q/g_k), Q scaled by D^-0.5 = 1/8.
// One thread per (b,h,s,d2) pair, d2 in [0,32).
// ---------------------------------------------------------------------------
__global__ __launch_bounds__(256)
void rope_kernel(const int* __restrict__ pos_ids)
{
    int idx = blockIdx.x * blockDim.x + threadIdx.x;
    const int total = B_ * H_ * S_ * 32;
    if (idx >= total) return;

    int d2 = idx & 31;
    int s  = (idx >> 5)  & (S_ - 1);
    int b  = idx >> 20;                 // 5 + 11 + 4 bits below

    int pos = pos_ids[b * S_ + s];
    // inv_freq = 10000^(-d2/32), computed in double to track jax's fp32 value
    float inv = (float)exp(-(double)d2 * (log(10000.0) / 32.0));
    float ang = (float)pos * inv;
    float sn, cs;
    sincosf(ang, &sn, &cs);

    int base = (idx >> 5) << 6;         // ((b*H+h)*S + s) * 64

    float q1 = g_q[base + d2];
    float q2 = g_q[base + 32 + d2];
    g_q[base + d2]      = 0.125f * (q1 * cs - q2 * sn);
    g_q[base + 32 + d2] = 0.125f * (q2 * cs + q1 * sn);

    float k1 = g_k[base + d2];
    float k2 = g_k[base + 32 + d2];
    g_k[base + d2]      = k1 * cs - k2 * sn;
    g_k[base + 32 + d2] = k2 * cs + k1 * sn;
}

// ---------------------------------------------------------------------------
// Kernel 3: flash attention, 64q x 64k tiles, fp32, online softmax.
// SMEM (dynamic, exactly 48KB): Qs[d][q] 64x64, KP[.]64x64 (K^T, then P^T),
// Vs[k][d] 64x64.
// ---------------------------------------------------------------------------
__global__ __launch_bounds__(256)
void attn_kernel(const float* __restrict__ mask, float* __restrict__ outp)
{
    extern __shared__ float sm[];
    float* Qs = sm;                // [64][64]  (d-major: Qs[d*64 + q])
    float* KP = sm + 64*64;        // [64][64]  Ks[d*64+k], later Ps[k*64+q]
    float* Vs = sm + 2*64*64;      // [64][64]  Vs[k*64+d]

    const int tid = threadIdx.x;
    const int tx  = tid & 15;
    const int ty  = tid >> 4;
    const int b   = blockIdx.z;
    const int h   = blockIdx.y;
    const int q0  = blockIdx.x * 64;

    const float* Qg = g_q + (((size_t)(b*H_ + h))*S_ + q0) * D_;
    const float* Kg = g_k + (((size_t)(b*H_ + h))*S_) * D_;
    const float* Vg = g_v + (((size_t)(b*H_ + h))*S_) * D_;
    const float* Mg = mask + ((size_t)b * S_ + q0) * S_;

    // Load Q tile (transposed to [d][q])
    {
        int r = tid >> 2;                  // 0..63 query row
        #pragma unroll
        for (int it = 0; it < 4; it++) {
            int c4 = (tid & 3) + it * 4;   // float4 index 0..15
            float4 v = *(const float4*)(Qg + r * D_ + c4 * 4);
            int d = c4 * 4;
            Qs[(d+0)*64 + r] = v.x; Qs[(d+1)*64 + r] = v.y;
            Qs[(d+2)*64 + r] = v.z; Qs[(d+3)*64 + r] = v.w;
        }
    }

    float m_i[4], l_i[4], o[4][4];
    #pragma unroll
    for (int i = 0; i < 4; i++) {
        m_i[i] = -1e30f; l_i[i] = 0.f;
        #pragma unroll
        for (int j = 0; j < 4; j++) o[i][j] = 0.f;
    }

    for (int t = 0; t < S_ / 64; t++) {
        const int kbase = t * 64;
        __syncthreads();  // also covers Q-tile stores on t=0, Vs/Ps reuse later

        // Load K tile transposed, V tile straight
        {
            int r = tid >> 2;
            #pragma unroll
            for (int it = 0; it < 4; it++) {
                int c4 = (tid & 3) + it * 4;
                float4 kv = *(const float4*)(Kg + (size_t)(kbase + r) * D_ + c4*4);
                int d = c4 * 4;
                KP[(d+0)*64 + r] = kv.x; KP[(d+1)*64 + r] = kv.y;
                KP[(d+2)*64 + r] = kv.z; KP[(d+3)*64 + r] = kv.w;
                float4 vv = *(const float4*)(Vg + (size_t)(kbase + r) * D_ + c4*4);
                *(float4*)&Vs[r*64 + c4*4] = vv;
            }
        }
        __syncthreads();

        // Scores: acc[i][j] = sum_d Q[q][d] K[k][d]
        float acc[4][4];
        #pragma unroll
        for (int i = 0; i < 4; i++)
            #pragma unroll
            for (int j = 0; j < 4; j++) acc[i][j] = 0.f;

        #pragma unroll 8
        for (int dd = 0; dd < 64; dd++) {
            float4 qv = *(const float4*)&Qs[dd*64 + ty*4];
            float4 kv = *(const float4*)&KP[dd*64 + tx*4];
            float qa[4] = {qv.x, qv.y, qv.z, qv.w};
            float ka[4] = {kv.x, kv.y, kv.z, kv.w};
            #pragma unroll
            for (int i = 0; i < 4; i++)
                #pragma unroll
                for (int j = 0; j < 4; j++)
                    acc[i][j] += qa[i] * ka[j];
        }

        // Add mask + online softmax (rows owned by same-ty 16-lane groups)
        #pragma unroll
        for (int i = 0; i < 4; i++) {
            float4 mv = *(const float4*)(Mg + (size_t)(ty*4 + i) * S_ + kbase + tx*4);
            acc[i][0] += mv.x; acc[i][1] += mv.y;
            acc[i][2] += mv.z; acc[i][3] += mv.w;

            float rmax = fmaxf(fmaxf(acc[i][0], acc[i][1]),
                               fmaxf(acc[i][2], acc[i][3]));
            #pragma unroll
            for (int off = 8; off >= 1; off >>= 1)
                rmax = fmaxf(rmax, __shfl_xor_sync(0xffffffffu, rmax, off, 16));

            float mnew = fmaxf(m_i[i], rmax);
            float rsum = 0.f;
            #pragma unroll
            for (int j = 0; j < 4; j++) {
                acc[i][j] = __expf(acc[i][j] - mnew);
                rsum += acc[i][j];
            }
            #pragma unroll
            for (int off = 8; off >= 1; off >>= 1)
                rsum += __shfl_xor_sync(0xffffffffu, rsum, off, 16);

            float alpha = __expf(m_i[i] - mnew);
            l_i[i] = l_i[i] * alpha + rsum;
            m_i[i] = mnew;
            #pragma unroll
            for (int j = 0; j < 4; j++) o[i][j] *= alpha;
        }

        __syncthreads();   // everyone done reading Ks before P overwrites it

        // Write P transposed: Ps[k][q]
        #pragma unroll
        for (int i = 0; i < 4; i++)
            #pragma unroll
            for (int j = 0; j < 4; j++)
                KP[(tx*4 + j)*64 + (ty*4 + i)] = acc[i][j];
        __syncthreads();

        // o[q][d] += sum_k P[q][k] * V[k][d]
        #pragma unroll 8
        for (int kk = 0; kk < 64; kk++) {
            float4 pv = *(const float4*)&KP[kk*64 + ty*4];
            float4 vv = *(const float4*)&Vs[kk*64 + tx*4];
            float pa[4] = {pv.x, pv.y, pv.z, pv.w};
            float va[4] = {vv.x, vv.y, vv.z, vv.w};
            #pragma unroll
            for (int i = 0; i < 4; i++)
                #pragma unroll
                for (int j = 0; j < 4; j++)
                    o[i][j] += pa[i] * va[j];
        }
    }

    // Normalize and write ctx: out[b][s][h*64 + d]
    #pragma unroll
    for (int i = 0; i < 4; i++) {
        float inv_l = 1.f / l_i[i];
        int q = q0 + ty*4 + i;
        float4 res = make_float4(o[i][0]*inv_l, o[i][1]*inv_l,
                                 o[i][2]*inv_l, o[i][3]*inv_l);
        *(float4*)&outp[((size_t)b * S_ + q) * DM_ + h*64 + tx*4] = res;
    }
}

// ---------------------------------------------------------------------------
extern "C" void kernel_launch(void* const* d_in, const int* in_sizes, int n_in,
                              void* d_out, int out_size)
{
    const float* hidden = (const float*)d_in[0];
    const float* mask   = (const float*)d_in[1];
    const int*   pos    = (const int*)  d_in[2];
    const float* Wq     = (const float*)d_in[3];
    const float* Wk     = (const float*)d_in[4];
    const float* Wv     = (const float*)d_in[5];
    float* out = (float*)d_out;

    dim3 g1(DM_ / 128, (B_ * S_) / 128, 3);
    qkv_gemm<<<g1, 256>>>(hidden, Wq, Wk, Wv);

    int total_pairs = B_ * H_ * S_ * 32;
    rope_kernel<<<(total_pairs + 255) / 256, 256>>>(pos);

    dim3 g2(S_ / 64, H_, B_);
    attn_kernel<<<g2, 256, 3 * 64 * 64 * sizeof(float)>>>(mask, out);
}